// round 6
// baseline (speedup 1.0000x reference)
#include <cuda_runtime.h>

// Dynamics_individual (MAK), N=8192, B=R=F=1
// d_in[0]=t (unused), d_in[1]=x [N], d_in[2]=A [N,N]
// d_out = [ f_self (N) | f_nbr (N*N) ], f_self[i]=1-x[i], f_nbr[i][j]=-x[i]*A[i][j]*x[j]
//
// Persistent single-wave kernel: 608 CTAs (152 SMs x 4) x 512 threads,
// grid-stride over rows. Per row: 4 front-batched LDG.128 per thread (MLP=4),
// streaming .cs hints both directions. Loop iterations are independent, so
// next-row loads overlap current-row stores via the scoreboard.

#define NDIM 8192u
#define QUADS_PER_ROW 2048u      // N/4
#define TPB 512u
#define QPT 4u                   // quads per thread (TPB*QPT == QUADS_PER_ROW)
#define GRID 608u                // 152 SMs * 4 CTAs -> exactly one wave

__global__ void __launch_bounds__(512) dyn_mak_kernel(
    const float* __restrict__ x,
    const float* __restrict__ A,
    float* __restrict__ out)
{
    const float4* __restrict__ A4 = reinterpret_cast<const float4*>(A);
    const float4* __restrict__ x4 = reinterpret_cast<const float4*>(x);
    float4* __restrict__ fnbr = reinterpret_cast<float4*>(out + NDIM);

    // Preload the row-local x quads once: same 4 quads for every row.
    float4 xj[QPT];
#pragma unroll
    for (int k = 0; k < (int)QPT; k++)
        xj[k] = x4[threadIdx.x + (unsigned)k * TPB];

    for (unsigned i = blockIdx.x; i < NDIM; i += GRID) {
        const unsigned base = i * QUADS_PER_ROW + threadIdx.x;
        const float s = -__ldg(&x[i]);

        // Front-batched: 4 independent LDG.128 in flight per thread.
        float4 a[QPT];
#pragma unroll
        for (int k = 0; k < (int)QPT; k++)
            a[k] = __ldcs(&A4[base + (unsigned)k * TPB]);

#pragma unroll
        for (int k = 0; k < (int)QPT; k++) {
            float4 r;
            r.x = s * a[k].x * xj[k].x;
            r.y = s * a[k].y * xj[k].y;
            r.z = s * a[k].z * xj[k].z;
            r.w = s * a[k].w * xj[k].w;
            __stcs(&fnbr[base + (unsigned)k * TPB], r);
        }
    }

    // f_self = 1 - x : 2048 quads, written once by block 0.
    if (blockIdx.x == 0) {
#pragma unroll
        for (int k = 0; k < (int)QPT; k++) {
            const unsigned q = threadIdx.x + (unsigned)k * TPB;
            float4 fs;
            fs.x = 1.0f - xj[k].x;
            fs.y = 1.0f - xj[k].y;
            fs.z = 1.0f - xj[k].z;
            fs.w = 1.0f - xj[k].w;
            reinterpret_cast<float4*>(out)[q] = fs;
        }
    }
}

extern "C" void kernel_launch(void* const* d_in, const int* in_sizes, int n_in,
                              void* d_out, int out_size)
{
    (void)in_sizes; (void)n_in; (void)out_size;
    const float* x = (const float*)d_in[1];
    const float* A = (const float*)d_in[2];
    float* out = (float*)d_out;

    dyn_mak_kernel<<<GRID, TPB>>>(x, A, out);
}

// round 7
// speedup vs baseline: 1.0721x; 1.0721x over previous
#include <cuda_runtime.h>

// Dynamics_individual (MAK), N=8192, B=R=F=1
// d_in[0]=t (unused), d_in[1]=x [N], d_in[2]=A [N,N]
// d_out = [ f_self (N) | f_nbr (N*N) ], f_self[i]=1-x[i], f_nbr[i][j]=-x[i]*A[i][j]*x[j]
//
// Final config: TPB=256 (highest measured occupancy, 83%), block = half row
// (row index uniform per block), QPT=4 front-batched LDG.128 (MLP=4),
// streaming .cs hints on A loads and f_nbr stores.

#define NDIM 8192u
#define QUADS_PER_ROW 2048u          // N/4
#define TPB 256u
#define QPT 4u
#define QUADS_PER_BLOCK (TPB * QPT)  // 1024 = half a row

__global__ void __launch_bounds__(256) dyn_mak_kernel(
    const float* __restrict__ x,
    const float* __restrict__ A,
    float* __restrict__ out)
{
    const unsigned i = blockIdx.x >> 1;                   // row, uniform per block
    const unsigned half = (blockIdx.x & 1u) * QUADS_PER_BLOCK;
    const unsigned base = i * QUADS_PER_ROW + half + threadIdx.x;

    const float4* __restrict__ A4 = reinterpret_cast<const float4*>(A);
    const float4* __restrict__ x4 = reinterpret_cast<const float4*>(x);
    float4* __restrict__ fnbr = reinterpret_cast<float4*>(out + NDIM);

    const float s = -__ldg(&x[i]);                        // uniform scalar

    // Front-batched: 4 independent LDG.128 in flight per thread.
    float4 a[QPT];
#pragma unroll
    for (int k = 0; k < (int)QPT; k++)
        a[k] = __ldcs(&A4[base + (unsigned)k * TPB]);

#pragma unroll
    for (int k = 0; k < (int)QPT; k++) {
        const unsigned j4 = half + threadIdx.x + (unsigned)k * TPB; // col quad
        const float4 xj = x4[j4];                                   // L1-resident
        float4 r;
        r.x = s * a[k].x * xj.x;
        r.y = s * a[k].y * xj.y;
        r.z = s * a[k].z * xj.z;
        r.w = s * a[k].w * xj.w;
        __stcs(&fnbr[base + (unsigned)k * TPB], r);
    }

    // f_self = 1 - x : 2048 quads, handled by blocks 0 and 1 (first row).
    if (blockIdx.x < 2) {
#pragma unroll
        for (int k = 0; k < (int)QPT; k++) {
            const unsigned q = half + threadIdx.x + (unsigned)k * TPB;
            const float4 xv = x4[q];
            float4 fs;
            fs.x = 1.0f - xv.x;
            fs.y = 1.0f - xv.y;
            fs.z = 1.0f - xv.z;
            fs.w = 1.0f - xv.w;
            reinterpret_cast<float4*>(out)[q] = fs;
        }
    }
}

extern "C" void kernel_launch(void* const* d_in, const int* in_sizes, int n_in,
                              void* d_out, int out_size)
{
    (void)in_sizes; (void)n_in; (void)out_size;
    const float* x = (const float*)d_in[1];
    const float* A = (const float*)d_in[2];
    float* out = (float*)d_out;

    const unsigned blocks = NDIM * 2u;   // two half-row blocks per row = 16384
    dyn_mak_kernel<<<blocks, TPB>>>(x, A, out);
}